// round 10
// baseline (speedup 1.0000x reference)
#include <cuda_runtime.h>
#include <math.h>
#include <stdint.h>
#include <mma.h>
using namespace nvcuda;

#define B_ 8
#define T_ 2048
#define D_ 128
#define H_ 4
#define HD_ 32
#define NTOK (B_*T_)
#define SCALE_ 0.17677669529663687f
#define EPS_ 1e-5f
#define LAMBDA_INIT_ 0.8f

__device__ float g_xln[NTOK * D_];
__device__ float g_q[B_ * H_ * T_ * 64];
__device__ float g_k[B_ * H_ * T_ * 64];
__device__ float g_v[B_ * H_ * T_ * 64];
__device__ float g_attn[NTOK * 256];

#define CVT_FRAG(fr) { for (int e_ = 0; e_ < (fr).num_elements; e_++) (fr).x[e_] = wmma::__float_to_tf32((fr).x[e_]); }

// ---------------- kernel 1: LayerNorm ----------------
__global__ __launch_bounds__(256) void ln_kernel(const float* __restrict__ tokens,
                                                 const float* __restrict__ w,
                                                 const float* __restrict__ b) {
    int warp = threadIdx.x >> 5, lane = threadIdx.x & 31;
    int t = blockIdx.x * 8 + warp;
    const float4* src = (const float4*)(tokens + (size_t)t * 128);
    float4 x = src[lane];
    float s = x.x + x.y + x.z + x.w;
    float q = x.x * x.x + x.y * x.y + x.z * x.z + x.w * x.w;
    #pragma unroll
    for (int o = 16; o; o >>= 1) {
        s += __shfl_xor_sync(0xFFFFFFFFu, s, o);
        q += __shfl_xor_sync(0xFFFFFFFFu, q, o);
    }
    float mu = s * (1.f / 128.f);
    float var = q * (1.f / 128.f) - mu * mu;
    float rstd = rsqrtf(var + EPS_);
    float4 wv = ((const float4*)w)[lane];
    float4 bv = ((const float4*)b)[lane];
    float4 y;
    y.x = (x.x - mu) * rstd * wv.x + bv.x;
    y.y = (x.y - mu) * rstd * wv.y + bv.y;
    y.z = (x.z - mu) * rstd * wv.z + bv.z;
    y.w = (x.w - mu) * rstd * wv.w + bv.w;
    ((float4*)g_xln)[(size_t)t * 32 + lane] = y;
}

// ---------------- kernel 2: QKV via wmma tf32 (unchanged from R8) ----------------
#define QKV_SMEM_BYTES (128 * 136 * 4)
__global__ __launch_bounds__(256) void qkv_wmma_kernel(const float* __restrict__ wq,
                                                       const float* __restrict__ wk,
                                                       const float* __restrict__ wv) {
    extern __shared__ float sX[];
    int tid = threadIdx.x, wid = tid >> 5;
    int bx = blockIdx.x, by = blockIdx.y;
    const float* Xb = g_xln + (size_t)by * 128 * 128;
    #pragma unroll
    for (int it = 0; it < 16; it++) {
        int f = tid + it * 256;
        int row = f >> 5, c4 = f & 31;
        float4 v = *(const float4*)(Xb + row * 128 + c4 * 4);
        *(float4*)(&sX[row * 136 + c4 * 4]) = v;
    }
    __syncthreads();
    int wr = wid >> 2, wc = wid & 3;
    int mat = bx >> 1;
    const float* W = (mat == 0) ? wq : (mat == 1 ? wk : wv);
    int ncol0 = (bx & 1) * 128;
    wmma::fragment<wmma::accumulator, 16, 16, 8, float> acc[4][2];
    #pragma unroll
    for (int i = 0; i < 4; i++)
        #pragma unroll
        for (int j = 0; j < 2; j++) wmma::fill_fragment(acc[i][j], 0.0f);
    for (int kt = 0; kt < 16; kt++) {
        wmma::fragment<wmma::matrix_a, 16, 16, 8, wmma::precision::tf32, wmma::row_major> a[4];
        #pragma unroll
        for (int i = 0; i < 4; i++) {
            wmma::load_matrix_sync(a[i], &sX[(wr * 64 + i * 16) * 136 + kt * 8], 136);
            CVT_FRAG(a[i]);
        }
        wmma::fragment<wmma::matrix_b, 16, 16, 8, wmma::precision::tf32, wmma::row_major> bfr[2];
        #pragma unroll
        for (int j = 0; j < 2; j++) {
            wmma::load_matrix_sync(bfr[j], W + (size_t)(kt * 8) * 256 + ncol0 + wc * 32 + j * 16, 256);
            CVT_FRAG(bfr[j]);
        }
        #pragma unroll
        for (int i = 0; i < 4; i++)
            #pragma unroll
            for (int j = 0; j < 2; j++) wmma::mma_sync(acc[i][j], a[i], bfr[j], acc[i][j]);
    }
    int b_ = by >> 4;
    #pragma unroll
    for (int i = 0; i < 4; i++) {
        int t0 = (by * 128 + wr * 64 + i * 16) & 2047;
        #pragma unroll
        for (int j = 0; j < 2; j++) {
            int gc = bx * 128 + wc * 32 + j * 16;
            int m2 = gc >> 8, cc = gc & 255;
            int h = cc >> 6, d = cc & 63;
            float* dst = (m2 == 0 ? g_q : (m2 == 1 ? g_k : g_v)) +
                         (((size_t)(b_ * 4 + h) * 2048 + t0) * 64 + d);
            wmma::store_matrix_sync(dst, acc[i][j], 64, wmma::mem_row_major);
        }
    }
}

// ---------------- kernel 3: attention, wmma for S and PV ----------------
// smem floats: sQ 64x68, sK 64x68, sV 64x68, sS1 64x68, sS2 64x68, sO 64x132, stats
#define OFF_Q  0
#define OFF_K  4352
#define OFF_V  8704
#define OFF_S1 13056
#define OFF_S2 17408
#define OFF_O  21760
#define OFF_ST 30208
#define ATTN2_SMEM_BYTES ((30208 + 6*64 + 8) * 4)

__global__ __launch_bounds__(256) void attn_wmma_kernel(
    const float* __restrict__ lq1, const float* __restrict__ lk1,
    const float* __restrict__ lq2, const float* __restrict__ lk2,
    const float* __restrict__ sig_s_p, const float* __restrict__ sig_n_p,
    const float* __restrict__ hn_w, const float* __restrict__ hn_b) {
    extern __shared__ float sm[];
    float* sQ  = sm + OFF_Q;
    float* sK  = sm + OFF_K;
    float* sV  = sm + OFF_V;
    float* sS1 = sm + OFF_S1;
    float* sS2 = sm + OFF_S2;
    float* sO  = sm + OFF_O;
    float* sM1 = sm + OFF_ST;
    float* sL1 = sM1 + 64;
    float* sM2 = sL1 + 64;
    float* sL2 = sM2 + 64;
    float* sR1 = sL2 + 64;
    float* sR2 = sR1 + 64;
    float* sLam = sR2 + 64;

    int qt = blockIdx.x, h = blockIdx.y, b = blockIdx.z;
    int qs = qt * 64;
    int tid = threadIdx.x, wid = tid >> 5;

    const float* qbase = g_q + ((size_t)(b * H_ + h) * T_ + qs) * 64;
    const float* kbase = g_k + ((size_t)(b * H_ + h) * T_) * 64;
    const float* vbase = g_v + ((size_t)(b * H_ + h) * T_) * 64;

    // load Q (pitch 68), zero O
    #pragma unroll
    for (int u = 0; u < 4; u++) {
        int f = tid + u * 256;
        int row = f >> 4, c4 = f & 15;
        float4 v = *(const float4*)(qbase + row * 64 + c4 * 4);
        *(float4*)(&sQ[row * 68 + c4 * 4]) = v;
    }
    for (int f = tid; f < 64 * 132; f += 256) sO[f] = 0.f;
    if (tid == 0) {
        float d1 = 0.f, d2 = 0.f;
        for (int i = 0; i < HD_; i++) { d1 += lq1[i] * lk1[i]; d2 += lq2[i] * lk2[i]; }
        *sLam = __expf(d1) - __expf(d2) + LAMBDA_INIT_;
    }
    if (tid < 64) { sM1[tid] = -1e30f; sL1[tid] = 0.f; sM2[tid] = -1e30f; sL2[tid] = 0.f; }

    float ss = fmaxf(sig_s_p[0], 1.f), sn = fmaxf(sig_n_p[0], 1.f);
    float inv2s = 0.5f / (ss * ss), inv2n = 0.5f / (sn * sn);
    float smax = fmaxf(ss, sn);
    int rcut = (int)(11.0f * smax) + 1;
    int klo = qs - rcut;       if (klo < 0) klo = 0;
    int khi = qs + 63 + rcut;  if (khi > T_ - 1) khi = T_ - 1;
    int kt_lo = klo >> 6, kt_hi = khi >> 6;

    int half = wid >> 2, strip = wid & 3;   // S phase roles
    __syncthreads();

    for (int ktile = kt_lo; ktile <= kt_hi; ktile++) {
        int ks = ktile * 64;
        // ---- load K, V (pitch 68) ----
        #pragma unroll
        for (int u = 0; u < 4; u++) {
            int f = tid + u * 256;
            int row = f >> 4, c4 = f & 15;
            float4 kv = *(const float4*)(kbase + (size_t)(ks + row) * 64 + c4 * 4);
            *(float4*)(&sK[row * 68 + c4 * 4]) = kv;
            float4 vv = *(const float4*)(vbase + (size_t)(ks + row) * 64 + c4 * 4);
            *(float4*)(&sV[row * 68 + c4 * 4]) = vv;
        }
        __syncthreads();

        // ---- S = Q K^T via wmma: warps 0-3 -> S1 strips, 4-7 -> S2 strips ----
        {
            float* Sdst = half ? sS2 : sS1;
            int d0 = half * 32;
            wmma::fragment<wmma::accumulator, 16, 16, 8, float> acc[4];
            #pragma unroll
            for (int j = 0; j < 4; j++) wmma::fill_fragment(acc[j], 0.0f);
            #pragma unroll
            for (int kt = 0; kt < 4; kt++) {
                wmma::fragment<wmma::matrix_a, 16, 16, 8, wmma::precision::tf32, wmma::row_major> a;
                wmma::load_matrix_sync(a, &sQ[(strip * 16) * 68 + d0 + kt * 8], 68);
                CVT_FRAG(a);
                #pragma unroll
                for (int j = 0; j < 4; j++) {
                    wmma::fragment<wmma::matrix_b, 16, 16, 8, wmma::precision::tf32, wmma::col_major> bf;
                    wmma::load_matrix_sync(bf, &sK[(j * 16) * 68 + d0 + kt * 8], 68);
                    CVT_FRAG(bf);
                    wmma::mma_sync(acc[j], a, bf, acc[j]);
                }
            }
            #pragma unroll
            for (int j = 0; j < 4; j++)
                wmma::store_matrix_sync(&Sdst[(strip * 16) * 68 + j * 16], acc[j], 68, wmma::mem_row_major);
        }
        __syncthreads();

        // ---- softmax (scale + bias fused here; 128 workers) ----
        if (tid < 128) {
            int r = tid >> 1;
            int two = tid & 1;
            float* S = two ? sS2 : sS1;
            float* M = two ? sM2 : sM1;
            float* L = two ? sL2 : sL1;
            float* R = two ? sR2 : sR1;
            float inv2 = two ? inv2n : inv2s;
            float mold = M[r];
            float mt = mold;
            float buf[64];
            #pragma unroll 8
            for (int k = 0; k < 64; k++) {
                float rel = (float)((ks + k) - (qs + r));
                float sv = S[r * 68 + k] * SCALE_ - inv2 * rel * rel;
                buf[k] = sv;
                mt = fmaxf(mt, sv);
            }
            float resc = __expf(mold - mt);
            float l = L[r] * resc;
            #pragma unroll 8
            for (int k = 0; k < 64; k++) {
                float p = __expf(buf[k] - mt);
                S[r * 68 + k] = p;
                l += p;
            }
            M[r] = mt; L[r] = l; R[r] = resc;
        }
        __syncthreads();

        // ---- rescale O in smem ----
        #pragma unroll
        for (int u = 0; u < 32; u++) {
            int f = tid + u * 256;
            int row = f >> 7, col = f & 127;
            float fac = (col < 64) ? sR1[row] : sR2[row];
            sO[row * 132 + col] *= fac;
        }
        __syncthreads();

        // ---- O += P V via wmma: warps 0-3 -> o1 strips, 4-7 -> o2 strips ----
        {
            float* P = half ? sS2 : sS1;
            int ocol0 = half * 64;
            wmma::fragment<wmma::accumulator, 16, 16, 8, float> acc[4];
            #pragma unroll
            for (int j = 0; j < 4; j++)
                wmma::load_matrix_sync(acc[j], &sO[(strip * 16) * 132 + ocol0 + j * 16], 132, wmma::mem_row_major);
            #pragma unroll
            for (int kt = 0; kt < 8; kt++) {
                wmma::fragment<wmma::matrix_a, 16, 16, 8, wmma::precision::tf32, wmma::row_major> a;
                wmma::load_matrix_sync(a, &P[(strip * 16) * 68 + kt * 8], 68);
                CVT_FRAG(a);
                #pragma unroll
                for (int j = 0; j < 4; j++) {
                    wmma::fragment<wmma::matrix_b, 16, 16, 8, wmma::precision::tf32, wmma::row_major> bf;
                    wmma::load_matrix_sync(bf, &sV[(kt * 8) * 68 + j * 16], 68);
                    CVT_FRAG(bf);
                    wmma::mma_sync(acc[j], a, bf, acc[j]);
                }
            }
            #pragma unroll
            for (int j = 0; j < 4; j++)
                wmma::store_matrix_sync(&sO[(strip * 16) * 132 + ocol0 + j * 16], acc[j], 132, wmma::mem_row_major);
        }
        __syncthreads();
    }

    // ---- epilogue: combine + headnorm + store ----
    if (tid < 64) {
        int r = tid;
        float lam = *sLam;
        float il1 = 1.f / sL1[r], il2 = 1.f / sL2[r];
        float mu = 0.f, sq = 0.f;
        float xbuf[64];
        #pragma unroll 8
        for (int j = 0; j < 64; j++) {
            float x = sO[r * 132 + j] * il1 - lam * sO[r * 132 + 64 + j] * il2;
            xbuf[j] = x;
            mu += x; sq += x * x;
        }
        mu *= (1.f / 64.f);
        float var = sq * (1.f / 64.f) - mu * mu;
        float rstd = rsqrtf(var + EPS_);
        float* dst = g_attn + (size_t)(b * T_ + qs + r) * 256 + h * 64;
        #pragma unroll 8
        for (int j = 0; j < 64; j++)
            dst[j] = ((xbuf[j] - mu) * rstd * hn_w[j] + hn_b[j]) * (1.0f - LAMBDA_INIT_);
    }
}

// ---------------- kernel 4: out GEMM wmma, grid 256 (occupancy fix) ----------------
__global__ __launch_bounds__(256) void out_wmma_kernel(const float* __restrict__ wo,
                                                       const float* __restrict__ tokens,
                                                       float* __restrict__ out) {
    int tid = threadIdx.x, wid = tid >> 5;
    int blk = blockIdx.x;                 // 256 blocks x 64 rows
    int wr = wid >> 1, wc = wid & 1;      // 4 row strips of 16, 2 col halves of 64

    wmma::fragment<wmma::accumulator, 16, 16, 8, float> acc[4];
    #pragma unroll
    for (int j = 0; j < 4; j++)
        wmma::load_matrix_sync(acc[j],
            tokens + (size_t)(blk * 64 + wr * 16) * 128 + wc * 64 + j * 16,
            128, wmma::mem_row_major);

    for (int kt = 0; kt < 32; kt++) {
        wmma::fragment<wmma::matrix_a, 16, 16, 8, wmma::precision::tf32, wmma::row_major> a;
        wmma::load_matrix_sync(a, g_attn + (size_t)(blk * 64 + wr * 16) * 256 + kt * 8, 256);
        CVT_FRAG(a);
        #pragma unroll
        for (int j = 0; j < 4; j++) {
            wmma::fragment<wmma::matrix_b, 16, 16, 8, wmma::precision::tf32, wmma::row_major> bf;
            wmma::load_matrix_sync(bf, wo + (size_t)(kt * 8) * 128 + wc * 64 + j * 16, 128);
            CVT_FRAG(bf);
            wmma::mma_sync(acc[j], a, bf, acc[j]);
        }
    }
    #pragma unroll
    for (int j = 0; j < 4; j++)
        wmma::store_matrix_sync(
            out + (size_t)(blk * 64 + wr * 16) * 128 + wc * 64 + j * 16,
            acc[j], 128, wmma::mem_row_major);
}

// ---------------- launch ----------------
extern "C" void kernel_launch(void* const* d_in, const int* in_sizes, int n_in,
                              void* d_out, int out_size) {
    const float* tokens = (const float*)d_in[0];
    const float* ln_w   = (const float*)d_in[1];
    const float* ln_b   = (const float*)d_in[2];
    const float* wq     = (const float*)d_in[3];
    const float* wk     = (const float*)d_in[4];
    const float* wv     = (const float*)d_in[5];
    const float* wo     = (const float*)d_in[6];
    const float* lq1    = (const float*)d_in[7];
    const float* lk1    = (const float*)d_in[8];
    const float* lq2    = (const float*)d_in[9];
    const float* lk2    = (const float*)d_in[10];
    const float* sigs   = (const float*)d_in[11];
    const float* sign   = (const float*)d_in[12];
    const float* hnw    = (const float*)d_in[13];
    const float* hnb    = (const float*)d_in[14];
    float* out = (float*)d_out;

    ln_kernel<<<NTOK / 8, 256>>>(tokens, ln_w, ln_b);

    cudaFuncSetAttribute(qkv_wmma_kernel, cudaFuncAttributeMaxDynamicSharedMemorySize, QKV_SMEM_BYTES);
    qkv_wmma_kernel<<<dim3(6, 128), 256, QKV_SMEM_BYTES>>>(wq, wk, wv);

    cudaFuncSetAttribute(attn_wmma_kernel, cudaFuncAttributeMaxDynamicSharedMemorySize, ATTN2_SMEM_BYTES);
    attn_wmma_kernel<<<dim3(32, H_, B_), 256, ATTN2_SMEM_BYTES>>>(lq1, lk1, lq2, lk2, sigs, sign, hnw, hnb);

    out_wmma_kernel<<<256, 256>>>(wo, tokens, out);
}